// round 2
// baseline (speedup 1.0000x reference)
#include <cuda_runtime.h>
#include <cstdint>

#define DINLINE __device__ __forceinline__

// ---------------- problem sizes ----------------
#define M_DIM 512
#define N_DIM 4096
#define K_DIM 4096

// ---------------- GEMM tiling ----------------
#define BM 128
#define BN 128
#define BK 64                       // int8 elements per K-chunk
#define ROWB 80                     // padded smem row stride (bytes) -> conflict-free ldmatrix
#define STAGES 4
#define KIT (K_DIM / BK)            // 64
#define TILE_BYTES (128 * ROWB)     // 10240 per operand tile
#define STAGE_BYTES (2 * TILE_BYTES)
#define SMEM_TOTAL (STAGES * STAGE_BYTES)   // 81920

// ---------------- scratch (static device globals; no allocs allowed) ----------------
__device__ __align__(256) int8_t g_xq[M_DIM * K_DIM];   // 2 MB
__device__ __align__(256) int8_t g_wq[N_DIM * K_DIM];   // 16 MB
__device__ unsigned int g_amax_bits[2];

// ---------------- PTX helpers ----------------
DINLINE uint32_t smem_u32(const void* p) {
    uint32_t a;
    asm("{ .reg .u64 t; cvta.to.shared.u64 t, %1; cvt.u32.u64 %0, t; }" : "=r"(a) : "l"(p));
    return a;
}

DINLINE void cp16(uint32_t dst, const void* src) {
    asm volatile("cp.async.cg.shared.global [%0], [%1], 16;" :: "r"(dst), "l"(src));
}
DINLINE void cp_commit() { asm volatile("cp.async.commit_group;" ::: "memory"); }

DINLINE void ldsm4(uint32_t* r, uint32_t addr) {
    asm volatile("ldmatrix.sync.aligned.m8n8.x4.shared.b16 {%0,%1,%2,%3}, [%4];"
                 : "=r"(r[0]), "=r"(r[1]), "=r"(r[2]), "=r"(r[3]) : "r"(addr));
}

DINLINE void imma(int* c, const uint32_t* a, const uint32_t* b) {
    asm volatile(
        "mma.sync.aligned.m16n8k32.row.col.s32.s8.s8.s32 "
        "{%0,%1,%2,%3}, {%4,%5,%6,%7}, {%8,%9}, {%0,%1,%2,%3};"
        : "+r"(c[0]), "+r"(c[1]), "+r"(c[2]), "+r"(c[3])
        : "r"(a[0]), "r"(a[1]), "r"(a[2]), "r"(a[3]), "r"(b[0]), "r"(b[1]));
}

// ---------------- phase 0: init ----------------
__global__ void init_kernel() {
    if (threadIdx.x == 0) { g_amax_bits[0] = 0u; g_amax_bits[1] = 0u; }
}

// ---------------- phase 1: amax (exact fp32 max of |t|) ----------------
__global__ void amax_kernel(const float4* __restrict__ in, int n4, int which) {
    float m = 0.0f;
    int stride = gridDim.x * blockDim.x;
    for (int i = blockIdx.x * blockDim.x + threadIdx.x; i < n4; i += stride) {
        float4 v = in[i];
        m = fmaxf(m, fmaxf(fmaxf(fabsf(v.x), fabsf(v.y)), fmaxf(fabsf(v.z), fabsf(v.w))));
    }
#pragma unroll
    for (int o = 16; o; o >>= 1) m = fmaxf(m, __shfl_xor_sync(0xffffffffu, m, o));
    __shared__ float sm[8];
    if ((threadIdx.x & 31) == 0) sm[threadIdx.x >> 5] = m;
    __syncthreads();
    if (threadIdx.x == 0) {
        float b = sm[0];
        for (int i = 1; i < (int)(blockDim.x >> 5); i++) b = fmaxf(b, sm[i]);
        // values are >= 0 -> int bit compare == float compare
        atomicMax(reinterpret_cast<int*>(&g_amax_bits[which]), __float_as_int(b));
    }
}

// ---------------- phase 2: quantize to integer codes (2 * e2m1 value) as int8 ----------------
// nearest codebook magnitude, ties -> lower value. Midpoints on |t|*scale:
//   0.25, 0.75, 1.25, 1.75, 2.5, 3.5, 5.0 ; strictly-greater moves up.
DINLINE int qcode(float v, float s) {
    float a = __fmul_rn(fabsf(v), s);
    int u = a > 5.0f  ? 12
          : a > 3.5f  ? 8
          : a > 2.5f  ? 6
          : a > 1.75f ? 4
          : a > 1.25f ? 3
          : a > 0.75f ? 2
          : a > 0.25f ? 1 : 0;
    return v < 0.0f ? -u : u;
}

__global__ void quantize_kernel(const float4* __restrict__ in, int n16, int which) {
    int8_t* outp = which ? g_wq : g_xq;
    float amax  = fmaxf(__uint_as_float(g_amax_bits[which]), 1e-12f);
    float s = __fdiv_rn(6.0f, amax);
    int stride = gridDim.x * blockDim.x;
    for (int i = blockIdx.x * blockDim.x + threadIdx.x; i < n16; i += stride) {
        uint32_t w[4];
#pragma unroll
        for (int j = 0; j < 4; j++) {
            float4 v = in[i * 4 + j];
            w[j] = ((uint32_t)(qcode(v.x, s) & 0xff))
                 | ((uint32_t)(qcode(v.y, s) & 0xff) << 8)
                 | ((uint32_t)(qcode(v.z, s) & 0xff) << 16)
                 | ((uint32_t)(qcode(v.w, s) & 0xff) << 24);
        }
        reinterpret_cast<uint4*>(outp)[i] = make_uint4(w[0], w[1], w[2], w[3]);
    }
}

// ---------------- phase 3: int8 IMMA GEMM ----------------
// C[128,128] per CTA; A = x codes [M,K], B = w codes [N,K], both K-major (row.col mma).
// 8 warps (2x4), warp tile 64x32 = 4x4 m16n8 tiles. BK=64 -> 2 k32 steps per stage.

__global__ void __launch_bounds__(256, 1) gemm_kernel(float* __restrict__ out) {
    extern __shared__ char smem[];
    uint32_t sb = smem_u32(smem);
    const int tid = threadIdx.x;
    const int lane = tid & 31, wid = tid >> 5;
    const int wm = wid >> 2, wn = wid & 3;
    const int bm = blockIdx.x & 3, bn = blockIdx.x >> 2;
    const int8_t* Ag = g_xq + (size_t)bm * BM * K_DIM;
    const int8_t* Bg = g_wq + (size_t)bn * BN * K_DIM;

    // cp.async mapping: 1024 x 16B chunks per stage (A 512 + B 512), 4 per thread
    uint32_t soff[4];
    const int8_t* gp[4];
#pragma unroll
    for (int j = 0; j < 4; j++) {
        int idx = tid + j * 256;
        int isB = idx >> 9;
        int rc = idx & 511;
        int row = rc >> 2, ch = rc & 3;
        soff[j] = (uint32_t)(isB * TILE_BYTES + row * ROWB + ch * 16);
        gp[j] = (isB ? Bg : Ag) + (size_t)row * K_DIM + ch * 16;
    }

    // per-lane ldmatrix offsets
    uint32_t offA[4][2], offB[2][2];
    {
        int rA = wm * 64 + (lane & 15);
        int kA = (lane & 16);
#pragma unroll
        for (int mt = 0; mt < 4; mt++)
#pragma unroll
            for (int ks = 0; ks < 2; ks++)
                offA[mt][ks] = (uint32_t)((rA + mt * 16) * ROWB + ks * 32 + kA);
        int mB = lane >> 3;
        int rB = wn * 32 + (mB >> 1) * 8 + (lane & 7);
        int kB = (mB & 1) * 16;
#pragma unroll
        for (int np = 0; np < 2; np++)
#pragma unroll
            for (int ks = 0; ks < 2; ks++)
                offB[np][ks] = (uint32_t)(TILE_BYTES + (rB + np * 16) * ROWB + ks * 32 + kB);
    }

    int acc[4][4][4];
#pragma unroll
    for (int mt = 0; mt < 4; mt++)
#pragma unroll
        for (int nt = 0; nt < 4; nt++)
#pragma unroll
            for (int i = 0; i < 4; i++) acc[mt][nt][i] = 0;

    // prologue: fill STAGES-1 stages
#pragma unroll
    for (int s = 0; s < STAGES - 1; s++) {
#pragma unroll
        for (int j = 0; j < 4; j++) cp16(sb + s * STAGE_BYTES + soff[j], gp[j] + s * BK);
        cp_commit();
    }

    for (int k = 0; k < KIT; k++) {
        const int s = k & (STAGES - 1);
        // pending-group bound such that stage k's group has completed
        if (k < KIT - 2)       asm volatile("cp.async.wait_group 2;" ::: "memory");
        else if (k == KIT - 2) asm volatile("cp.async.wait_group 1;" ::: "memory");
        else                   asm volatile("cp.async.wait_group 0;" ::: "memory");
        __syncthreads();

        // prefetch stage k+3 into the slot retired at iteration k-1
        int kp = k + STAGES - 1;
        if (kp < KIT) {
            uint32_t sp = sb + (kp & (STAGES - 1)) * STAGE_BYTES;
#pragma unroll
            for (int j = 0; j < 4; j++) cp16(sp + soff[j], gp[j] + kp * BK);
            cp_commit();
        }

        uint32_t base = sb + s * STAGE_BYTES;
#pragma unroll
        for (int ks = 0; ks < 2; ks++) {
            uint32_t a[4][4], b[2][4];
#pragma unroll
            for (int mt = 0; mt < 4; mt++) ldsm4(a[mt], base + offA[mt][ks]);
#pragma unroll
            for (int np = 0; np < 2; np++) ldsm4(b[np], base + offB[np][ks]);
#pragma unroll
            for (int mt = 0; mt < 4; mt++) {
#pragma unroll
                for (int nt = 0; nt < 4; nt++) {
                    const uint32_t* bf = &b[nt >> 1][(nt & 1) * 2];
                    imma(acc[mt][nt], a[mt], bf);
                }
            }
        }
    }

    // epilogue: scale by inv_scale_x * inv_scale_w / 4 (codes are 2x codebook values)
    float ax = fmaxf(__uint_as_float(g_amax_bits[0]), 1e-12f);
    float aw = fmaxf(__uint_as_float(g_amax_bits[1]), 1e-12f);
    float invx = __fdiv_rn(1.0f, __fdiv_rn(6.0f, ax));
    float invw = __fdiv_rn(1.0f, __fdiv_rn(6.0f, aw));
    float scl = invx * invw * 0.25f;

    int row0 = bm * BM + wm * 64 + (lane >> 2);
    int col0 = bn * BN + wn * 32 + (lane & 3) * 2;
#pragma unroll
    for (int mt = 0; mt < 4; mt++) {
#pragma unroll
        for (int nt = 0; nt < 4; nt++) {
            float2 v0, v1;
            v0.x = __int2float_rn(acc[mt][nt][0]) * scl;
            v0.y = __int2float_rn(acc[mt][nt][1]) * scl;
            v1.x = __int2float_rn(acc[mt][nt][2]) * scl;
            v1.y = __int2float_rn(acc[mt][nt][3]) * scl;
            int r = row0 + mt * 16;
            int c = col0 + nt * 8;
            *reinterpret_cast<float2*>(out + (size_t)r * N_DIM + c) = v0;
            *reinterpret_cast<float2*>(out + (size_t)(r + 8) * N_DIM + c) = v1;
        }
    }
}

// ---------------- launch ----------------
extern "C" void kernel_launch(void* const* d_in, const int* in_sizes, int n_in,
                              void* d_out, int out_size) {
    const float* x = (const float*)d_in[0];       // [512, 4096]
    const float* w = (const float*)d_in[1];       // [4096, 4096]
    float* out = (float*)d_out;                   // [512, 4096] fp32

    cudaFuncSetAttribute(gemm_kernel, cudaFuncAttributeMaxDynamicSharedMemorySize, SMEM_TOTAL);

    init_kernel<<<1, 32>>>();
    amax_kernel<<<296, 256>>>((const float4*)x, (M_DIM * K_DIM) / 4, 0);
    amax_kernel<<<592, 256>>>((const float4*)w, (N_DIM * K_DIM) / 4, 1);
    quantize_kernel<<<296, 256>>>((const float4*)x, (M_DIM * K_DIM) / 16, 0);
    quantize_kernel<<<592, 256>>>((const float4*)w, (N_DIM * K_DIM) / 16, 1);
    gemm_kernel<<<(M_DIM / BM) * (N_DIM / BN), 256, SMEM_TOTAL>>>(out);
}

// round 3
// speedup vs baseline: 1.0897x; 1.0897x over previous
#include <cuda_runtime.h>
#include <cstdint>

#define DINLINE __device__ __forceinline__

// ---------------- problem sizes ----------------
#define M_DIM 512
#define N_DIM 4096
#define K_DIM 4096

// ---------------- GEMM tiling ----------------
#define BM 128
#define BN 128
#define BK 64                       // int8 elements per K-chunk
#define ROWB 80                     // padded smem row stride (bytes) -> conflict-free ldmatrix
#define STAGES 4
#define KIT (K_DIM / BK)            // 64
#define TILE_BYTES (128 * ROWB)     // 10240 per operand tile
#define STAGE_BYTES (2 * TILE_BYTES)
#define SMEM_TOTAL (STAGES * STAGE_BYTES)   // 81920

// ---------------- amax/quantize grids (exact cover) ----------------
#define AMAX_X_BLOCKS 256           // 256 blk * 256 thr * 8 f4 = 524288 f4 = 8 MB
#define AMAX_W_BLOCKS 2048          // 2048 * 256 * 8 = 4194304 f4 = 64 MB
#define QUANT_X_BLOCKS 512          // 512 blk * 256 thr * 1 uint4-out (16 int8) = 2 MB out
#define QUANT_W_BLOCKS 4096

// ---------------- scratch (static device globals; no allocs allowed) ----------------
__device__ __align__(256) int8_t g_xq[M_DIM * K_DIM];   // 2 MB
__device__ __align__(256) int8_t g_wq[N_DIM * K_DIM];   // 16 MB
__device__ unsigned int g_amax_bits[2];

// ---------------- PTX helpers ----------------
DINLINE uint32_t smem_u32(const void* p) {
    uint32_t a;
    asm("{ .reg .u64 t; cvta.to.shared.u64 t, %1; cvt.u32.u64 %0, t; }" : "=r"(a) : "l"(p));
    return a;
}

DINLINE void cp16(uint32_t dst, const void* src) {
    asm volatile("cp.async.cg.shared.global [%0], [%1], 16;" :: "r"(dst), "l"(src));
}
DINLINE void cp_commit() { asm volatile("cp.async.commit_group;" ::: "memory"); }

DINLINE void ldsm4(uint32_t* r, uint32_t addr) {
    asm volatile("ldmatrix.sync.aligned.m8n8.x4.shared.b16 {%0,%1,%2,%3}, [%4];"
                 : "=r"(r[0]), "=r"(r[1]), "=r"(r[2]), "=r"(r[3]) : "r"(addr));
}

DINLINE void imma(int* c, const uint32_t* a, const uint32_t* b) {
    asm volatile(
        "mma.sync.aligned.m16n8k32.row.col.s32.s8.s8.s32 "
        "{%0,%1,%2,%3}, {%4,%5,%6,%7}, {%8,%9}, {%0,%1,%2,%3};"
        : "+r"(c[0]), "+r"(c[1]), "+r"(c[2]), "+r"(c[3])
        : "r"(a[0]), "r"(a[1]), "r"(a[2]), "r"(a[3]), "r"(b[0]), "r"(b[1]));
}

// ---------------- phase 0: init ----------------
__global__ void init_kernel() {
    if (threadIdx.x == 0) { g_amax_bits[0] = 0u; g_amax_bits[1] = 0u; }
}

// ---------------- phase 1: fused amax (exact fp32 max of |t|), MLP=8 ----------------
__global__ void __launch_bounds__(256) amax_kernel(const float4* __restrict__ x,
                                                   const float4* __restrict__ w) {
    const float4* in;
    int which;
    if (blockIdx.x < AMAX_X_BLOCKS) {
        in = x + (size_t)blockIdx.x * 2048;
        which = 0;
    } else {
        in = w + (size_t)(blockIdx.x - AMAX_X_BLOCKS) * 2048;
        which = 1;
    }
    float4 v[8];
#pragma unroll
    for (int j = 0; j < 8; j++) v[j] = in[threadIdx.x + j * 256];
    float m = 0.0f;
#pragma unroll
    for (int j = 0; j < 8; j++)
        m = fmaxf(m, fmaxf(fmaxf(fabsf(v[j].x), fabsf(v[j].y)),
                           fmaxf(fabsf(v[j].z), fabsf(v[j].w))));
#pragma unroll
    for (int o = 16; o; o >>= 1) m = fmaxf(m, __shfl_xor_sync(0xffffffffu, m, o));
    __shared__ float sm[8];
    if ((threadIdx.x & 31) == 0) sm[threadIdx.x >> 5] = m;
    __syncthreads();
    if (threadIdx.x == 0) {
        float b = sm[0];
#pragma unroll
        for (int i = 1; i < 8; i++) b = fmaxf(b, sm[i]);
        // values >= 0 -> int bit compare == float compare
        atomicMax(reinterpret_cast<int*>(&g_amax_bits[which]), __float_as_int(b));
    }
}

// ---------------- phase 2: fused quantize to integer codes (2 * e2m1 value) as int8 ----------------
// nearest codebook magnitude, ties -> lower. Midpoints on |t|*scale:
//   0.25, 0.75, 1.25, 1.75, 2.5, 3.5, 5.0 ; strictly-greater moves up.
DINLINE int qcode(float v, float s) {
    float a = __fmul_rn(fabsf(v), s);
    int u = a > 5.0f  ? 12
          : a > 3.5f  ? 8
          : a > 2.5f  ? 6
          : a > 1.75f ? 4
          : a > 1.25f ? 3
          : a > 0.75f ? 2
          : a > 0.25f ? 1 : 0;
    return v < 0.0f ? -u : u;
}

__global__ void __launch_bounds__(256) quantize_kernel(const float4* __restrict__ x,
                                                       const float4* __restrict__ w) {
    const float4* in;
    int8_t* outp;
    size_t i;
    int which;
    if (blockIdx.x < QUANT_X_BLOCKS) {
        in = x; outp = g_xq; which = 0;
        i = (size_t)blockIdx.x * 256 + threadIdx.x;
    } else {
        in = w; outp = g_wq; which = 1;
        i = (size_t)(blockIdx.x - QUANT_X_BLOCKS) * 256 + threadIdx.x;
    }
    float amax = fmaxf(__uint_as_float(g_amax_bits[which]), 1e-12f);
    float s = __fdiv_rn(6.0f, amax);

    float4 v[4];
#pragma unroll
    for (int j = 0; j < 4; j++) v[j] = in[i * 4 + j];
    uint32_t wrd[4];
#pragma unroll
    for (int j = 0; j < 4; j++) {
        wrd[j] = ((uint32_t)(qcode(v[j].x, s) & 0xff))
               | ((uint32_t)(qcode(v[j].y, s) & 0xff) << 8)
               | ((uint32_t)(qcode(v[j].z, s) & 0xff) << 16)
               | ((uint32_t)(qcode(v[j].w, s) & 0xff) << 24);
    }
    reinterpret_cast<uint4*>(outp)[i] = make_uint4(wrd[0], wrd[1], wrd[2], wrd[3]);
}

// ---------------- phase 3: int8 IMMA GEMM ----------------
// C[128,128] per CTA; A = x codes [M,K], B = w codes [N,K], both K-major (row.col mma).
// 8 warps (2x4), warp tile 64x32 = 4x4 m16n8 tiles. BK=64 -> 2 k32 steps per stage.

__global__ void __launch_bounds__(256, 1) gemm_kernel(float* __restrict__ out) {
    extern __shared__ char smem[];
    uint32_t sb = smem_u32(smem);
    const int tid = threadIdx.x;
    const int lane = tid & 31, wid = tid >> 5;
    const int wm = wid >> 2, wn = wid & 3;
    const int bm = blockIdx.x & 3, bn = blockIdx.x >> 2;
    const int8_t* Ag = g_xq + (size_t)bm * BM * K_DIM;
    const int8_t* Bg = g_wq + (size_t)bn * BN * K_DIM;

    // cp.async mapping: 1024 x 16B chunks per stage (A 512 + B 512), 4 per thread
    uint32_t soff[4];
    const int8_t* gp[4];
#pragma unroll
    for (int j = 0; j < 4; j++) {
        int idx = tid + j * 256;
        int isB = idx >> 9;
        int rc = idx & 511;
        int row = rc >> 2, ch = rc & 3;
        soff[j] = (uint32_t)(isB * TILE_BYTES + row * ROWB + ch * 16);
        gp[j] = (isB ? Bg : Ag) + (size_t)row * K_DIM + ch * 16;
    }

    // per-lane ldmatrix offsets
    uint32_t offA[4][2], offB[2][2];
    {
        int rA = wm * 64 + (lane & 15);
        int kA = (lane & 16);
#pragma unroll
        for (int mt = 0; mt < 4; mt++)
#pragma unroll
            for (int ks = 0; ks < 2; ks++)
                offA[mt][ks] = (uint32_t)((rA + mt * 16) * ROWB + ks * 32 + kA);
        int mB = lane >> 3;
        int rB = wn * 32 + (mB >> 1) * 8 + (lane & 7);
        int kB = (mB & 1) * 16;
#pragma unroll
        for (int np = 0; np < 2; np++)
#pragma unroll
            for (int ks = 0; ks < 2; ks++)
                offB[np][ks] = (uint32_t)(TILE_BYTES + (rB + np * 16) * ROWB + ks * 32 + kB);
    }

    int acc[4][4][4];
#pragma unroll
    for (int mt = 0; mt < 4; mt++)
#pragma unroll
        for (int nt = 0; nt < 4; nt++)
#pragma unroll
            for (int i = 0; i < 4; i++) acc[mt][nt][i] = 0;

    // prologue: fill STAGES-1 stages
#pragma unroll
    for (int s = 0; s < STAGES - 1; s++) {
#pragma unroll
        for (int j = 0; j < 4; j++) cp16(sb + s * STAGE_BYTES + soff[j], gp[j] + s * BK);
        cp_commit();
    }

    for (int k = 0; k < KIT; k++) {
        const int s = k & (STAGES - 1);
        // pending-group bound such that stage k's group has completed
        if (k < KIT - 2)       asm volatile("cp.async.wait_group 2;" ::: "memory");
        else if (k == KIT - 2) asm volatile("cp.async.wait_group 1;" ::: "memory");
        else                   asm volatile("cp.async.wait_group 0;" ::: "memory");
        __syncthreads();

        // prefetch stage k+3 into the slot retired at iteration k-1
        int kp = k + STAGES - 1;
        if (kp < KIT) {
            uint32_t sp = sb + (kp & (STAGES - 1)) * STAGE_BYTES;
#pragma unroll
            for (int j = 0; j < 4; j++) cp16(sp + soff[j], gp[j] + kp * BK);
            cp_commit();
        }

        uint32_t base = sb + s * STAGE_BYTES;
#pragma unroll
        for (int ks = 0; ks < 2; ks++) {
            uint32_t a[4][4], b[2][4];
#pragma unroll
            for (int mt = 0; mt < 4; mt++) ldsm4(a[mt], base + offA[mt][ks]);
#pragma unroll
            for (int np = 0; np < 2; np++) ldsm4(b[np], base + offB[np][ks]);
#pragma unroll
            for (int mt = 0; mt < 4; mt++) {
#pragma unroll
                for (int nt = 0; nt < 4; nt++) {
                    const uint32_t* bf = &b[nt >> 1][(nt & 1) * 2];
                    imma(acc[mt][nt], a[mt], bf);
                }
            }
        }
    }

    // epilogue: scale by inv_scale_x * inv_scale_w / 4 (codes are 2x codebook values)
    float ax = fmaxf(__uint_as_float(g_amax_bits[0]), 1e-12f);
    float aw = fmaxf(__uint_as_float(g_amax_bits[1]), 1e-12f);
    float invx = __fdiv_rn(1.0f, __fdiv_rn(6.0f, ax));
    float invw = __fdiv_rn(1.0f, __fdiv_rn(6.0f, aw));
    float scl = invx * invw * 0.25f;

    int row0 = bm * BM + wm * 64 + (lane >> 2);
    int col0 = bn * BN + wn * 32 + (lane & 3) * 2;
#pragma unroll
    for (int mt = 0; mt < 4; mt++) {
#pragma unroll
        for (int nt = 0; nt < 4; nt++) {
            float2 v0, v1;
            v0.x = __int2float_rn(acc[mt][nt][0]) * scl;
            v0.y = __int2float_rn(acc[mt][nt][1]) * scl;
            v1.x = __int2float_rn(acc[mt][nt][2]) * scl;
            v1.y = __int2float_rn(acc[mt][nt][3]) * scl;
            int r = row0 + mt * 16;
            int c = col0 + nt * 8;
            *reinterpret_cast<float2*>(out + (size_t)r * N_DIM + c) = v0;
            *reinterpret_cast<float2*>(out + (size_t)(r + 8) * N_DIM + c) = v1;
        }
    }
}

// ---------------- launch ----------------
extern "C" void kernel_launch(void* const* d_in, const int* in_sizes, int n_in,
                              void* d_out, int out_size) {
    const float* x = (const float*)d_in[0];       // [512, 4096]
    const float* w = (const float*)d_in[1];       // [4096, 4096]
    float* out = (float*)d_out;                   // [512, 4096] fp32

    cudaFuncSetAttribute(gemm_kernel, cudaFuncAttributeMaxDynamicSharedMemorySize, SMEM_TOTAL);

    init_kernel<<<1, 32>>>();
    amax_kernel<<<AMAX_X_BLOCKS + AMAX_W_BLOCKS, 256>>>((const float4*)x, (const float4*)w);
    quantize_kernel<<<QUANT_X_BLOCKS + QUANT_W_BLOCKS, 256>>>((const float4*)x, (const float4*)w);
    gemm_kernel<<<(M_DIM / BM) * (N_DIM / BN), 256, SMEM_TOTAL>>>(out);
}

// round 4
// speedup vs baseline: 2.0543x; 1.8852x over previous
#include <cuda_runtime.h>
#include <cstdint>

#define DINLINE __device__ __forceinline__

// ---------------- problem sizes ----------------
#define M_DIM 512
#define N_DIM 4096
#define K_DIM 4096

// ---------------- GEMM tiling ----------------
#define BM 64
#define BN 128
#define BK 64                        // fp8 elements per K-chunk
#define ROWB 80                      // padded smem row stride (bytes) -> conflict-free ldmatrix
#define STAGES 4
#define KIT (K_DIM / BK)             // 64
#define TILE_A_BYTES (BM * ROWB)     // 5120
#define TILE_B_BYTES (BN * ROWB)     // 10240
#define STAGE_BYTES (TILE_A_BYTES + TILE_B_BYTES)   // 15360
#define SMEM_TOTAL (STAGES * STAGE_BYTES)           // 61440 -> 2 CTAs/SM

// ---------------- amax/quantize grids (exact cover) ----------------
#define AMAX_X_BLOCKS 256
#define AMAX_W_BLOCKS 2048
#define QUANT_X_BLOCKS 512
#define QUANT_W_BLOCKS 4096

// ---------------- scratch (static device globals; no allocs allowed) ----------------
// codes: e4m3 encodings of 2*e2m1 codebook value, i.e. {0,1,2,3,4,6,8,12} signed
__device__ __align__(256) uint8_t g_xq[M_DIM * K_DIM];   // 2 MB
__device__ __align__(256) uint8_t g_wq[N_DIM * K_DIM];   // 16 MB
__device__ unsigned int g_amax_bits[2];

// ---------------- PTX helpers ----------------
DINLINE uint32_t smem_u32(const void* p) {
    uint32_t a;
    asm("{ .reg .u64 t; cvta.to.shared.u64 t, %1; cvt.u32.u64 %0, t; }" : "=r"(a) : "l"(p));
    return a;
}

DINLINE void cp16(uint32_t dst, const void* src) {
    asm volatile("cp.async.cg.shared.global [%0], [%1], 16;" :: "r"(dst), "l"(src));
}
DINLINE void cp_commit() { asm volatile("cp.async.commit_group;" ::: "memory"); }

DINLINE void ldsm4(uint32_t* r, uint32_t addr) {
    asm volatile("ldmatrix.sync.aligned.m8n8.x4.shared.b16 {%0,%1,%2,%3}, [%4];"
                 : "=r"(r[0]), "=r"(r[1]), "=r"(r[2]), "=r"(r[3]) : "r"(addr));
}

// fp8 e4m3 MMA, f32 accumulate. Operand layouts identical to the s8 m16n8k32 variant.
DINLINE void mma_f8(float* c, const uint32_t* a, const uint32_t* b) {
    asm volatile(
        "mma.sync.aligned.m16n8k32.row.col.f32.e4m3.e4m3.f32 "
        "{%0,%1,%2,%3}, {%4,%5,%6,%7}, {%8,%9}, {%0,%1,%2,%3};"
        : "+f"(c[0]), "+f"(c[1]), "+f"(c[2]), "+f"(c[3])
        : "r"(a[0]), "r"(a[1]), "r"(a[2]), "r"(a[3]), "r"(b[0]), "r"(b[1]));
}

// ---------------- phase 0: init ----------------
__global__ void init_kernel() {
    if (threadIdx.x == 0) { g_amax_bits[0] = 0u; g_amax_bits[1] = 0u; }
}

// ---------------- phase 1: fused amax (exact fp32 max of |t|), MLP=8 ----------------
__global__ void __launch_bounds__(256) amax_kernel(const float4* __restrict__ x,
                                                   const float4* __restrict__ w) {
    const float4* in;
    int which;
    if (blockIdx.x < AMAX_X_BLOCKS) {
        in = x + (size_t)blockIdx.x * 2048;
        which = 0;
    } else {
        in = w + (size_t)(blockIdx.x - AMAX_X_BLOCKS) * 2048;
        which = 1;
    }
    float4 v[8];
#pragma unroll
    for (int j = 0; j < 8; j++) v[j] = in[threadIdx.x + j * 256];
    float m = 0.0f;
#pragma unroll
    for (int j = 0; j < 8; j++)
        m = fmaxf(m, fmaxf(fmaxf(fabsf(v[j].x), fabsf(v[j].y)),
                           fmaxf(fabsf(v[j].z), fabsf(v[j].w))));
#pragma unroll
    for (int o = 16; o; o >>= 1) m = fmaxf(m, __shfl_xor_sync(0xffffffffu, m, o));
    __shared__ float sm[8];
    if ((threadIdx.x & 31) == 0) sm[threadIdx.x >> 5] = m;
    __syncthreads();
    if (threadIdx.x == 0) {
        float b = sm[0];
#pragma unroll
        for (int i = 1; i < 8; i++) b = fmaxf(b, sm[i]);
        atomicMax(reinterpret_cast<int*>(&g_amax_bits[which]), __float_as_int(b));
    }
}

// ---------------- phase 2: fused quantize to e4m3 codes ----------------
// nearest codebook magnitude, ties -> lower. Midpoints on |t|*scale:
//   0.25, 0.75, 1.25, 1.75, 2.5, 3.5, 5.0 ; strictly-greater moves up.
// e4m3 encodings of {0,1,2,3,4,6,8,12}: 00,38,40,44,48,4C,50,54
DINLINE uint32_t qbyte(float v, float s) {
    float a = __fmul_rn(fabsf(v), s);
    int idx = a > 5.0f  ? 7
            : a > 3.5f  ? 6
            : a > 2.5f  ? 5
            : a > 1.75f ? 4
            : a > 1.25f ? 3
            : a > 0.75f ? 2
            : a > 0.25f ? 1 : 0;
    uint32_t b = (uint32_t)((0x54504C4844403800ull >> (idx * 8)) & 0xff);
    return b | (v < 0.0f ? 0x80u : 0u);
}

__global__ void __launch_bounds__(256) quantize_kernel(const float4* __restrict__ x,
                                                       const float4* __restrict__ w) {
    const float4* in;
    uint8_t* outp;
    size_t i;
    int which;
    if (blockIdx.x < QUANT_X_BLOCKS) {
        in = x; outp = g_xq; which = 0;
        i = (size_t)blockIdx.x * 256 + threadIdx.x;
    } else {
        in = w; outp = g_wq; which = 1;
        i = (size_t)(blockIdx.x - QUANT_X_BLOCKS) * 256 + threadIdx.x;
    }
    float amax = fmaxf(__uint_as_float(g_amax_bits[which]), 1e-12f);
    float s = __fdiv_rn(6.0f, amax);

    float4 v[4];
#pragma unroll
    for (int j = 0; j < 4; j++) v[j] = in[i * 4 + j];
    uint32_t wrd[4];
#pragma unroll
    for (int j = 0; j < 4; j++) {
        wrd[j] = qbyte(v[j].x, s)
               | (qbyte(v[j].y, s) << 8)
               | (qbyte(v[j].z, s) << 16)
               | (qbyte(v[j].w, s) << 24);
    }
    reinterpret_cast<uint4*>(outp)[i] = make_uint4(wrd[0], wrd[1], wrd[2], wrd[3]);
}

// ---------------- phase 3: fp8 QMMA GEMM ----------------
// C[64,128] per CTA; A = x codes [M,K], B = w codes [N,K], both K-major (row.col mma).
// 8 warps (2x4), warp tile 32x32 = 2x4 m16n8 tiles. BK=64 -> 2 k32 steps per stage.
// 256 CTAs, 2 CTAs/SM -> all 148 SMs busy, barriers overlapped.

__global__ void __launch_bounds__(256, 2) gemm_kernel(float* __restrict__ out) {
    extern __shared__ char smem[];
    uint32_t sb = smem_u32(smem);
    const int tid = threadIdx.x;
    const int lane = tid & 31, wid = tid >> 5;
    const int wm = wid >> 2, wn = wid & 3;
    const int bm = blockIdx.x & 7, bn = blockIdx.x >> 3;
    const uint8_t* Ag = g_xq + (size_t)bm * BM * K_DIM;
    const uint8_t* Bg = g_wq + (size_t)bn * BN * K_DIM;

    // cp.async mapping: 768 x 16B chunks per stage (A 256 + B 512), 3 per thread
    uint32_t soff[3];
    const uint8_t* gp[3];
#pragma unroll
    for (int j = 0; j < 3; j++) {
        int idx = tid + j * 256;
        if (idx < 256) {                      // A: 64 rows x 4 chunks
            int row = idx >> 2, ch = idx & 3;
            soff[j] = (uint32_t)(row * ROWB + ch * 16);
            gp[j] = Ag + (size_t)row * K_DIM + ch * 16;
        } else {                              // B: 128 rows x 4 chunks
            int r2 = idx - 256;
            int row = r2 >> 2, ch = r2 & 3;
            soff[j] = (uint32_t)(TILE_A_BYTES + row * ROWB + ch * 16);
            gp[j] = Bg + (size_t)row * K_DIM + ch * 16;
        }
    }

    // per-lane ldmatrix offsets
    uint32_t offA[2][2], offB[2][2];
    {
        int rA = wm * 32 + (lane & 15);
        int kA = (lane & 16);
#pragma unroll
        for (int mt = 0; mt < 2; mt++)
#pragma unroll
            for (int ks = 0; ks < 2; ks++)
                offA[mt][ks] = (uint32_t)((rA + mt * 16) * ROWB + ks * 32 + kA);
        int mB = lane >> 3;
        int rB = wn * 32 + (mB >> 1) * 8 + (lane & 7);
        int kB = (mB & 1) * 16;
#pragma unroll
        for (int np = 0; np < 2; np++)
#pragma unroll
            for (int ks = 0; ks < 2; ks++)
                offB[np][ks] = (uint32_t)(TILE_A_BYTES + (rB + np * 16) * ROWB + ks * 32 + kB);
    }

    float acc[2][4][4];
#pragma unroll
    for (int mt = 0; mt < 2; mt++)
#pragma unroll
        for (int nt = 0; nt < 4; nt++)
#pragma unroll
            for (int i = 0; i < 4; i++) acc[mt][nt][i] = 0.0f;

    // prologue: fill STAGES-1 stages
#pragma unroll
    for (int s = 0; s < STAGES - 1; s++) {
#pragma unroll
        for (int j = 0; j < 3; j++) cp16(sb + s * STAGE_BYTES + soff[j], gp[j] + s * BK);
        cp_commit();
    }

    for (int k = 0; k < KIT; k++) {
        const int s = k & (STAGES - 1);
        if (k < KIT - 2)       asm volatile("cp.async.wait_group 2;" ::: "memory");
        else if (k == KIT - 2) asm volatile("cp.async.wait_group 1;" ::: "memory");
        else                   asm volatile("cp.async.wait_group 0;" ::: "memory");
        __syncthreads();

        // prefetch stage k+3 into the slot retired at iteration k-1
        int kp = k + STAGES - 1;
        if (kp < KIT) {
            uint32_t sp = sb + (kp & (STAGES - 1)) * STAGE_BYTES;
#pragma unroll
            for (int j = 0; j < 3; j++) cp16(sp + soff[j], gp[j] + kp * BK);
            cp_commit();
        }

        uint32_t base = sb + s * STAGE_BYTES;
#pragma unroll
        for (int ks = 0; ks < 2; ks++) {
            uint32_t a[2][4], b[2][4];
#pragma unroll
            for (int mt = 0; mt < 2; mt++) ldsm4(a[mt], base + offA[mt][ks]);
#pragma unroll
            for (int np = 0; np < 2; np++) ldsm4(b[np], base + offB[np][ks]);
#pragma unroll
            for (int mt = 0; mt < 2; mt++) {
#pragma unroll
                for (int nt = 0; nt < 4; nt++) {
                    const uint32_t* bf = &b[nt >> 1][(nt & 1) * 2];
                    mma_f8(acc[mt][nt], a[mt], bf);
                }
            }
        }
    }

    // epilogue: scale by inv_scale_x * inv_scale_w / 4 (codes are 2x codebook values)
    float ax = fmaxf(__uint_as_float(g_amax_bits[0]), 1e-12f);
    float aw = fmaxf(__uint_as_float(g_amax_bits[1]), 1e-12f);
    float invx = __fdiv_rn(1.0f, __fdiv_rn(6.0f, ax));
    float invw = __fdiv_rn(1.0f, __fdiv_rn(6.0f, aw));
    float scl = invx * invw * 0.25f;

    int row0 = bm * BM + wm * 32 + (lane >> 2);
    int col0 = bn * BN + wn * 32 + (lane & 3) * 2;
#pragma unroll
    for (int mt = 0; mt < 2; mt++) {
#pragma unroll
        for (int nt = 0; nt < 4; nt++) {
            float2 v0, v1;
            v0.x = acc[mt][nt][0] * scl;
            v0.y = acc[mt][nt][1] * scl;
            v1.x = acc[mt][nt][2] * scl;
            v1.y = acc[mt][nt][3] * scl;
            int r = row0 + mt * 16;
            int c = col0 + nt * 8;
            *reinterpret_cast<float2*>(out + (size_t)r * N_DIM + c) = v0;
            *reinterpret_cast<float2*>(out + (size_t)(r + 8) * N_DIM + c) = v1;
        }
    }
}

// ---------------- launch ----------------
extern "C" void kernel_launch(void* const* d_in, const int* in_sizes, int n_in,
                              void* d_out, int out_size) {
    const float* x = (const float*)d_in[0];       // [512, 4096]
    const float* w = (const float*)d_in[1];       // [4096, 4096]
    float* out = (float*)d_out;                   // [512, 4096] fp32

    cudaFuncSetAttribute(gemm_kernel, cudaFuncAttributeMaxDynamicSharedMemorySize, SMEM_TOTAL);

    init_kernel<<<1, 32>>>();
    amax_kernel<<<AMAX_X_BLOCKS + AMAX_W_BLOCKS, 256>>>((const float4*)x, (const float4*)w);
    quantize_kernel<<<QUANT_X_BLOCKS + QUANT_W_BLOCKS, 256>>>((const float4*)x, (const float4*)w);
    gemm_kernel<<<(M_DIM / BM) * (N_DIM / BN), 256, SMEM_TOTAL>>>(out);
}